// round 9
// baseline (speedup 1.0000x reference)
#include <cuda_runtime.h>
#include <cuda_bf16.h>
#include <cstdint>

#define NN   2048
#define FIN  16
#define TT   12
#define FOUT 32
#define BB   8
#define FT   192
#define WSTR 40      // k_main padded row stride in halves (80 B, conflict-free ldmatrix)
#define S2STR 72     // k_s2 padded row stride in halves (144 B, conflict-free ldmatrix)

typedef unsigned int u32;

// ------------------------------ scratch globals ------------------------------
__device__ float g_S  [NN*(size_t)NN];
__device__ float g_ST [NN*(size_t)NN];
__device__ float g_S2T[NN*(size_t)NN];
__device__ __nv_bfloat16 g_Shi [NN*(size_t)NN];
__device__ __nv_bfloat16 g_Slo [NN*(size_t)NN];
__device__ __nv_bfloat16 g_SThi[NN*(size_t)NN];
__device__ __nv_bfloat16 g_STlo[NN*(size_t)NN];
__device__ __nv_bfloat16 g_xThi[BB*(size_t)FT*NN];
__device__ __nv_bfloat16 g_xTlo[BB*(size_t)FT*NN];
__device__ float g_r1[BB*(size_t)NN*FT];
__device__ float g_r2[BB*(size_t)NN*FT];

// ------------------------------ helpers ------------------------------
__device__ __forceinline__ u32 smem_u32(const void* p) {
    u32 a;
    asm("{ .reg .u64 t; cvta.to.shared.u64 t, %1; cvt.u32.u64 %0, t; }" : "=r"(a) : "l"(p));
    return a;
}
__device__ __forceinline__ void cp16(u32 dst, const void* src) {
    asm volatile("cp.async.cg.shared.global [%0], [%1], 16;" :: "r"(dst), "l"(src));
}
#define CP_COMMIT() asm volatile("cp.async.commit_group;" ::: "memory")
#define CP_WAIT(n)  asm volatile("cp.async.wait_group %0;" :: "n"(n) : "memory")

__device__ __forceinline__ void ldsm_x4(u32* r, u32 addr) {
    asm volatile("ldmatrix.sync.aligned.m8n8.x4.shared.b16 {%0,%1,%2,%3}, [%4];"
        : "=r"(r[0]), "=r"(r[1]), "=r"(r[2]), "=r"(r[3]) : "r"(addr));
}
__device__ __forceinline__ void ldsm_x2(u32* r, u32 addr) {
    asm volatile("ldmatrix.sync.aligned.m8n8.x2.shared.b16 {%0,%1}, [%2];"
        : "=r"(r[0]), "=r"(r[1]) : "r"(addr));
}
__device__ __forceinline__ void mma_bf16(float* d, const u32* a, const u32* b) {
    asm volatile("mma.sync.aligned.m16n8k16.row.col.f32.bf16.bf16.f32 "
        "{%0,%1,%2,%3}, {%4,%5,%6,%7}, {%8,%9}, {%0,%1,%2,%3};"
        : "+f"(d[0]), "+f"(d[1]), "+f"(d[2]), "+f"(d[3])
        : "r"(a[0]), "r"(a[1]), "r"(a[2]), "r"(a[3]), "r"(b[0]), "r"(b[1]));
}
__device__ __forceinline__ void split_bf16(float v, __nv_bfloat16& h, __nv_bfloat16& l) {
    h = __float2bfloat16(v);
    l = __float2bfloat16(v - __bfloat162float(h));
}

// ---------------------------------------------------------------------------
// Kernel 1: S = softmax(relu(E E^T), axis=1); also emits Shi/Slo (fused)
// ---------------------------------------------------------------------------
__global__ __launch_bounds__(256)
void k_supports(const float* __restrict__ E) {
    const int i   = blockIdx.x;
    const int tid = threadIdx.x;
    __shared__ float ei[FIN];
    __shared__ float row[NN];
    __shared__ float red[8];
    __shared__ float bc0, bc1;

    if (tid < FIN) ei[tid] = E[i*FIN + tid];
    __syncthreads();

    float lmax = 0.0f;
    for (int j = tid; j < NN; j += 256) {
        const float4* ej = reinterpret_cast<const float4*>(E + (size_t)j*FIN);
        float dot = 0.f;
        #pragma unroll
        for (int q = 0; q < 4; q++) {
            float4 v = ej[q];
            dot += v.x*ei[q*4+0] + v.y*ei[q*4+1] + v.z*ei[q*4+2] + v.w*ei[q*4+3];
        }
        float r = fmaxf(dot, 0.f);
        row[j] = r;
        lmax = fmaxf(lmax, r);
    }
    #pragma unroll
    for (int o = 16; o > 0; o >>= 1) lmax = fmaxf(lmax, __shfl_xor_sync(0xffffffffu, lmax, o));
    if ((tid & 31) == 0) red[tid >> 5] = lmax;
    __syncthreads();
    if (tid == 0) {
        float m = red[0];
        #pragma unroll
        for (int w = 1; w < 8; w++) m = fmaxf(m, red[w]);
        bc0 = m;
    }
    __syncthreads();
    const float bmax = bc0;

    float lsum = 0.f;
    for (int j = tid; j < NN; j += 256) {
        float e = expf(row[j] - bmax);
        row[j] = e;
        lsum += e;
    }
    #pragma unroll
    for (int o = 16; o > 0; o >>= 1) lsum += __shfl_xor_sync(0xffffffffu, lsum, o);
    if ((tid & 31) == 0) red[tid >> 5] = lsum;
    __syncthreads();
    if (tid == 0) {
        float s = 0.f;
        #pragma unroll
        for (int w = 0; w < 8; w++) s += red[w];
        bc1 = 1.0f / s;
    }
    __syncthreads();
    const float inv = bc1;
    for (int j = tid; j < NN; j += 256) {
        float v = row[j] * inv;
        size_t o = (size_t)i*NN + j;
        g_S[o] = v;
        __nv_bfloat16 h, l; split_bf16(v, h, l);
        g_Shi[o] = h; g_Slo[o] = l;
    }
}

// ---------------------------------------------------------------------------
// Kernel 2: ST/SThi/STlo (transposed split of S)
// ---------------------------------------------------------------------------
__global__ __launch_bounds__(256)
void k_prepS() {
    __shared__ float t[64][65];
    const int tid = threadIdx.x;
    const int i0 = blockIdx.y*64, j0 = blockIdx.x*64;

    for (int idx = tid; idx < 1024; idx += 256) {
        int r = idx >> 4, q = idx & 15;
        float4 v = *reinterpret_cast<const float4*>(&g_S[(size_t)(i0+r)*NN + j0 + q*4]);
        t[r][q*4+0] = v.x; t[r][q*4+1] = v.y; t[r][q*4+2] = v.z; t[r][q*4+3] = v.w;
    }
    __syncthreads();
    for (int idx = tid; idx < 4096; idx += 256) {
        int c = idx >> 6, r = idx & 63;
        float v = t[r][c];
        __nv_bfloat16 h, l; split_bf16(v, h, l);
        size_t o = (size_t)(j0+c)*NN + i0 + r;
        g_ST[o] = v; g_SThi[o] = h; g_STlo[o] = l;
    }
}

// ---------------------------------------------------------------------------
// Kernel 3: xT[b][ft][n] hi/lo split
// ---------------------------------------------------------------------------
__global__ __launch_bounds__(256)
void k_prepx(const float* __restrict__ x) {
    __shared__ float t[FT][33];
    const int tid = threadIdx.x;
    const int b  = blockIdx.y;
    const int n0 = blockIdx.x*32;
    const float* xb = x + (size_t)b*NN*FT;

    for (int idx = tid; idx < 32*48; idx += 256) {
        int r = idx / 48, q = idx % 48;
        float4 v = *reinterpret_cast<const float4*>(&xb[(size_t)(n0+r)*FT + q*4]);
        t[q*4+0][r] = v.x; t[q*4+1][r] = v.y; t[q*4+2][r] = v.z; t[q*4+3][r] = v.w;
    }
    __syncthreads();
    for (int idx = tid; idx < FT*32; idx += 256) {
        int ft = idx >> 5, n = idx & 31;
        __nv_bfloat16 h, l; split_bf16(t[ft][n], h, l);
        size_t o = ((size_t)b*FT + ft)*NN + n0 + n;
        g_xThi[o] = h; g_xTlo[o] = l;
    }
}

// ---------------------------------------------------------------------------
// Kernel 4: S2T[i][j] = sum_k ST[i,k]*S[j,k]  (3-pass bf16, cp.async double buffer)
// CTA 128x128, 512 threads, 16 warps (4x4), warp tile 32x32, KC=64.
// 4 warps/SMSP for HMMA latency hiding (was 2 -> tensor pipe 53%).
// ---------------------------------------------------------------------------
#define S2_BUFH (4*128*S2STR)   // halves per buffer (ATH,ATL,BH,BL)
#define S2_ATH 0
#define S2_ATL (128*S2STR)
#define S2_BH  (2*128*S2STR)
#define S2_BL  (3*128*S2STR)

__global__ __launch_bounds__(512, 1)
void k_s2() {
    extern __shared__ __align__(16) __nv_bfloat16 sh[];
    const int tid = threadIdx.x, w = tid >> 5, lane = tid & 31;
    const int wm = w >> 2, wn = w & 3;
    const int i0 = blockIdx.y*128, j0 = blockIdx.x*128;
    const u32 sb = smem_u32(sh);

    float d[2][4][4];
    #pragma unroll
    for (int mt = 0; mt < 2; mt++)
        #pragma unroll
        for (int nt = 0; nt < 4; nt++)
            #pragma unroll
            for (int e = 0; e < 4; e++) d[mt][nt][e] = 0.f;

    auto stage = [&](int ch) {
        const int n0 = ch*64;
        const u32 bufb = sb + (u32)((ch & 1) * S2_BUFH * 2);
        #pragma unroll
        for (int idx = tid; idx < 4096; idx += 512) {
            int arr = idx >> 10, i = idx & 1023, row = i >> 3, q = i & 7;
            const __nv_bfloat16* src;
            int grow;
            if      (arr == 0) { src = g_SThi; grow = i0 + row; }
            else if (arr == 1) { src = g_STlo; grow = i0 + row; }
            else if (arr == 2) { src = g_Shi;  grow = j0 + row; }
            else               { src = g_Slo;  grow = j0 + row; }
            u32 dst = bufb + (u32)((arr*128*S2STR + row*S2STR + q*8)*2);
            cp16(dst, src + (size_t)grow*NN + n0 + q*8);
        }
    };

    stage(0); CP_COMMIT();

    for (int ch = 0; ch < 32; ch++) {
        if (ch < 31) { stage(ch+1); CP_COMMIT(); CP_WAIT(1); }
        else         { CP_WAIT(0); }
        __syncthreads();

        const u32 bufb = sb + (u32)((ch & 1) * S2_BUFH * 2);
        #pragma unroll
        for (int ks = 0; ks < 4; ks++) {
            u32 ah[2][4], bh[4][2], bl[4][2];
            const int arow = wm*32 + (lane & 15);
            const int acol = ks*16 + (lane >> 4)*8;
            const int brow = wn*32 + (lane & 7);
            const int bcol = ks*16 + ((lane >> 3) & 1)*8;
            #pragma unroll
            for (int nt = 0; nt < 4; nt++) {
                u32 bd = bufb + (u32)(((brow + nt*8)*S2STR + bcol)*2);
                ldsm_x2(bh[nt], bd + S2_BH*2);
                ldsm_x2(bl[nt], bd + S2_BL*2);
            }
            #pragma unroll
            for (int mt = 0; mt < 2; mt++) {
                u32 ad = bufb + (u32)(((arow + mt*16)*S2STR + acol)*2);
                ldsm_x4(ah[mt], ad + S2_ATH*2);
            }
            // pass 1: hi*hi
            #pragma unroll
            for (int mt = 0; mt < 2; mt++)
                #pragma unroll
                for (int nt = 0; nt < 4; nt++)
                    mma_bf16(d[mt][nt], ah[mt], bh[nt]);
            // pass 2: hi*lo
            #pragma unroll
            for (int mt = 0; mt < 2; mt++)
                #pragma unroll
                for (int nt = 0; nt < 4; nt++)
                    mma_bf16(d[mt][nt], ah[mt], bl[nt]);
            // pass 3: lo*hi (reload A-lo into same regs)
            #pragma unroll
            for (int mt = 0; mt < 2; mt++) {
                u32 ad = bufb + (u32)(((arow + mt*16)*S2STR + acol)*2);
                ldsm_x4(ah[mt], ad + S2_ATL*2);
            }
            #pragma unroll
            for (int mt = 0; mt < 2; mt++)
                #pragma unroll
                for (int nt = 0; nt < 4; nt++)
                    mma_bf16(d[mt][nt], ah[mt], bh[nt]);
        }
        __syncthreads();
    }
    #pragma unroll
    for (int mt = 0; mt < 2; mt++)
        #pragma unroll
        for (int nt = 0; nt < 4; nt++) {
            int row = i0 + wm*32 + mt*16 + (lane >> 2);
            int col = j0 + wn*32 + nt*8 + (lane & 3)*2;
            *reinterpret_cast<float2*>(&g_S2T[(size_t)row*NN + col]) =
                make_float2(d[mt][nt][0], d[mt][nt][1]);
            *reinterpret_cast<float2*>(&g_S2T[(size_t)(row+8)*NN + col]) =
                make_float2(d[mt][nt][2], d[mt][nt][3]);
        }
}

// ---------------------------------------------------------------------------
// Kernel 5: masked dual-GEMM, cp.async pipeline, A transposed in-SMEM
//   W rows 0-63 : W1[m,n] = ST[m,n]*A[b,n,m]        -> r1
//   W rows 64-127: W2[m,n] = 2*S2T[m,n]*A[b,n,m]    -> r2
// CTA: 256 thr, 2 CTAs/SM, M=128, N=96, KC=32, 8 warps (2x4), warp tile 64x24
// ---------------------------------------------------------------------------
#define KM_W(p)    ((p)*10240)
#define KM_X(p)    (20480 + (p)*7680)
#define KM_RAWB    71680
#define KM_STB     (KM_RAWB)
#define KM_S2B     (KM_RAWB + 8192)
#define KM_AB      (KM_RAWB + 16384)
#define KM_SMEM    (KM_RAWB + 25088)   // 96768 B

__global__ __launch_bounds__(256, 2)
void k_main(const float* __restrict__ A) {
    extern __shared__ __align__(16) __nv_bfloat16 sh[];
    char* shc = reinterpret_cast<char*>(sh);
    const int tid = threadIdx.x, w = tid >> 5, lane = tid & 31;
    const int wm = w >> 2, wn = w & 3;
    const int m0 = blockIdx.x*64;
    const int nh = blockIdx.y;
    const int b  = blockIdx.z;
    const u32 sb = smem_u32(sh);

    const float* Ab = A + (size_t)b*NN*NN;
    const __nv_bfloat16* xh = g_xThi + ((size_t)b*FT + nh*96)*NN;
    const __nv_bfloat16* xl = g_xTlo + ((size_t)b*FT + nh*96)*NN;
    float* stST = reinterpret_cast<float*>(shc + KM_STB);
    float* stS2 = reinterpret_cast<float*>(shc + KM_S2B);
    float* As   = reinterpret_cast<float*>(shc + KM_AB);

    float d[4][3][4];
    #pragma unroll
    for (int mt = 0; mt < 4; mt++)
        #pragma unroll
        for (int nt = 0; nt < 3; nt++)
            #pragma unroll
            for (int e = 0; e < 4; e++) d[mt][nt][e] = 0.f;

    auto stage = [&](int ch) {
        const int n0 = ch*32;
        const int p = ch & 1;
        #pragma unroll
        for (int idx = tid; idx < 2304; idx += 256) {
            if (idx < 768) {                 // X hi/lo
                int sel = idx >= 384;
                int i = idx - sel*384;
                int row = i >> 2, q = i & 3;
                const __nv_bfloat16* src = sel ? xl : xh;
                u32 dst = sb + (u32)((KM_X(p) + sel*3840 + row*WSTR + q*8)*2);
                cp16(dst, src + (size_t)row*NN + n0 + q*8);
            } else if (idx < 1792) {         // raw ST/S2T
                int j = idx - 768;
                int sel = j >> 9;
                int i = j & 511;
                int row = i >> 3, q = i & 7;
                const float* src = sel ? g_S2T : g_ST;
                u32 dst = sb + (u32)((sel ? KM_S2B : KM_STB) + (row*32 + q*4)*4);
                cp16(dst, src + (size_t)(m0+row)*NN + n0 + q*4);
            } else {                         // raw A
                int j = idx - 1792;
                int row = j >> 4, q = j & 15;
                u32 dst = sb + (u32)(KM_AB + (row*68 + q*4)*4);
                cp16(dst, Ab + (size_t)(n0+row)*NN + m0 + q*4);
            }
        }
    };

    auto build = [&](int ch) {
        const int p = ch & 1;
        #pragma unroll
        for (int idx = tid; idx < 1024; idx += 256) {
            int m = idx >> 4, pp = idx & 15, n = 2*pp;
            float2 st = *reinterpret_cast<const float2*>(&stST[m*32 + n]);
            float2 s2 = *reinterpret_cast<const float2*>(&stS2[m*32 + n]);
            float a0 = As[n*68 + m], a1 = As[(n+1)*68 + m];
            float w1x = st.x*a0, w1y = st.y*a1;
            float w2x = 2.f*s2.x*a0, w2y = 2.f*s2.y*a1;
            __nv_bfloat16 h1x,l1x,h1y,l1y,h2x,l2x,h2y,l2y;
            split_bf16(w1x,h1x,l1x); split_bf16(w1y,h1y,l1y);
            split_bf16(w2x,h2x,l2x); split_bf16(w2y,h2y,l2y);
            int base = KM_W(p);
            *reinterpret_cast<__nv_bfloat162*>(shc + (base + m*WSTR + n)*2)          = __nv_bfloat162(h1x, h1y);
            *reinterpret_cast<__nv_bfloat162*>(shc + (base + 5120 + m*WSTR + n)*2)   = __nv_bfloat162(l1x, l1y);
            *reinterpret_cast<__nv_bfloat162*>(shc + (base + (64+m)*WSTR + n)*2)     = __nv_bfloat162(h2x, h2y);
            *reinterpret_cast<__nv_bfloat162*>(shc + (base + 5120 + (64+m)*WSTR + n)*2) = __nv_bfloat162(l2x, l2y);
        }
    };

    auto domma = [&](int ch) {
        const int p = ch & 1;
        const u32 wbase = sb + (u32)(KM_W(p)*2);
        const u32 xbase = sb + (u32)(KM_X(p)*2);
        #pragma unroll
        for (int ks = 0; ks < 2; ks++) {
            u32 ah[4][4], bh[3][2], bl[3][2];
            const int arow = wm*64 + (lane & 15);
            const int acol = ks*16 + (lane >> 4)*8;
            const int brow = wn*24 + (lane & 7);
            const int bcol = ks*16 + ((lane >> 3) & 1)*8;
            #pragma unroll
            for (int nt = 0; nt < 3; nt++) {
                u32 bd = xbase + (u32)(((brow + nt*8)*WSTR + bcol)*2);
                ldsm_x2(bh[nt], bd);
                ldsm_x2(bl[nt], bd + 3840*2);
            }
            #pragma unroll
            for (int mt = 0; mt < 4; mt++) {
                u32 ad = wbase + (u32)(((arow + mt*16)*WSTR + acol)*2);
                ldsm_x4(ah[mt], ad);
            }
            // pass 1: Whi * Xhi
            #pragma unroll
            for (int mt = 0; mt < 4; mt++)
                #pragma unroll
                for (int nt = 0; nt < 3; nt++)
                    mma_bf16(d[mt][nt], ah[mt], bh[nt]);
            // pass 2: Whi * Xlo
            #pragma unroll
            for (int mt = 0; mt < 4; mt++)
                #pragma unroll
                for (int nt = 0; nt < 3; nt++)
                    mma_bf16(d[mt][nt], ah[mt], bl[nt]);
            // pass 3: Wlo * Xhi
            #pragma unroll
            for (int mt = 0; mt < 4; mt++) {
                u32 ad = wbase + (u32)(((arow + mt*16)*WSTR + acol)*2);
                ldsm_x4(ah[mt], ad + 5120*2);
            }
            #pragma unroll
            for (int mt = 0; mt < 4; mt++)
                #pragma unroll
                for (int nt = 0; nt < 3; nt++)
                    mma_bf16(d[mt][nt], ah[mt], bh[nt]);
        }
    };

    stage(0); CP_COMMIT();
    CP_WAIT(0); __syncthreads();
    build(0); __syncthreads();

    for (int c = 0; c < 64; c++) {
        if (c < 63) { stage(c+1); CP_COMMIT(); }
        domma(c);
        if (c < 63) {
            CP_WAIT(0); __syncthreads();
            build(c+1);
            __syncthreads();
        }
    }

    // epilogue
    #pragma unroll
    for (int mt = 0; mt < 4; mt++)
        #pragma unroll
        for (int nt = 0; nt < 3; nt++) {
            int mrow = wm*64 + mt*16 + (lane >> 2);
            int col  = nh*96 + wn*24 + nt*8 + (lane & 3)*2;
            float* base = (mrow < 64) ? g_r1 : g_r2;
            size_t off = ((size_t)b*NN + m0 + (mrow & 63))*FT + col;
            *reinterpret_cast<float2*>(base + off) = make_float2(d[mt][nt][0], d[mt][nt][1]);
            *reinterpret_cast<float2*>(base + off + 8*FT) = make_float2(d[mt][nt][2], d[mt][nt][3]);
        }
}

// ---------------------------------------------------------------------------
// Kernel 6: theta contraction + diagonal identity term + relu
// ---------------------------------------------------------------------------
__global__ __launch_bounds__(256)
void k_theta(const float* __restrict__ x, const float* __restrict__ A,
             const float* __restrict__ theta, float* __restrict__ out) {
    extern __shared__ float smf[];
    float* r1   = smf;
    float* r2   = smf + 6144;
    float* s0   = smf + 12288;
    float* th1  = smf + 18432;
    float* th2  = smf + 18944;
    float* th02 = smf + 19456;

    const int b   = blockIdx.y;
    const int m0  = blockIdx.x * 32;
    const int tid = threadIdx.x;
    const float* xb = x + (size_t)b*NN*FT;
    const float* Ab = A + (size_t)b*NN*NN;

    for (int i = tid; i < 1536; i += 256) {
        reinterpret_cast<float4*>(r1)[i] =
            reinterpret_cast<const float4*>(g_r1 + ((size_t)b*NN + m0)*FT)[i];
        reinterpret_cast<float4*>(r2)[i] =
            reinterpret_cast<const float4*>(g_r2 + ((size_t)b*NN + m0)*FT)[i];
    }
    for (int i = tid; i < FIN*FOUT; i += 256) {
        th1[i] = theta[512 + i];
        float t2 = theta[1024 + i];
        th2[i]  = t2;
        th02[i] = theta[i] - t2;
    }
    for (int i = tid; i < 32*FT; i += 256) {
        int m = i / FT, ftc = i - m*FT;
        float dg = Ab[(size_t)(m0+m)*NN + m0 + m];
        s0[i] = dg * xb[(size_t)(m0+m)*FT + ftc];
    }
    __syncthreads();

    float* outb = out + (size_t)b*NN*FOUT*TT;
    for (int idx = tid; idx < 32*FOUT*TT; idx += 256) {
        int m = idx / (FOUT*TT);
        int r = idx - m*(FOUT*TT);
        int o = r / TT, t = r - o*TT;
        float val = 0.f;
        #pragma unroll
        for (int f = 0; f < FIN; f++) {
            int ft = f*TT + t;
            val = fmaf(r1[m*FT + ft], th1[f*FOUT + o], val);
            val = fmaf(r2[m*FT + ft], th2[f*FOUT + o], val);
            val = fmaf(s0[m*FT + ft], th02[f*FOUT + o], val);
        }
        outb[(size_t)(m0+m)*FOUT*TT + r] = fmaxf(val, 0.f);
    }
}

// ---------------------------------------------------------------------------
extern "C" void kernel_launch(void* const* d_in, const int* in_sizes, int n_in,
                              void* d_out, int out_size) {
    const float *x = nullptr, *A = nullptr, *E = nullptr, *theta = nullptr;
    for (int i = 0; i < n_in; i++) {
        switch (in_sizes[i]) {
            case BB*NN*FIN*TT:   x     = (const float*)d_in[i]; break;
            case BB*NN*NN:       A     = (const float*)d_in[i]; break;
            case NN*FIN:         E     = (const float*)d_in[i]; break;
            case 3*FIN*FOUT:     theta = (const float*)d_in[i]; break;
        }
    }
    float* out = (float*)d_out;

    k_supports<<<NN, 256>>>(E);
    k_prepS<<<dim3(32, 32), 256>>>();
    k_prepx<<<dim3(64, BB), 256>>>(x);

    const int s2_smem = 2 * S2_BUFH * 2;   // 147456 B
    cudaFuncSetAttribute(k_s2, cudaFuncAttributeMaxDynamicSharedMemorySize, s2_smem);
    k_s2<<<dim3(16, 16), 512, s2_smem>>>();

    cudaFuncSetAttribute(k_main, cudaFuncAttributeMaxDynamicSharedMemorySize, KM_SMEM);
    k_main<<<dim3(32, 2, BB), 256, KM_SMEM>>>(A);

    const int smem_th = 19968 * (int)sizeof(float);
    cudaFuncSetAttribute(k_theta, cudaFuncAttributeMaxDynamicSharedMemorySize, smem_th);
    k_theta<<<dim3(NN/32, BB), 256, smem_th>>>(x, A, theta, out);
}

// round 10
// speedup vs baseline: 1.2859x; 1.2859x over previous
#include <cuda_runtime.h>
#include <cuda_fp16.h>
#include <cstdint>

#define NN   2048
#define FIN  16
#define TT   12
#define FOUT 32
#define BB   8
#define FT   192
#define WSTR 40      // padded row stride in halves (80 B, conflict-free ldmatrix)

typedef unsigned int u32;

// ------------------------------ scratch globals ------------------------------
__device__ float g_S  [NN*(size_t)NN];
__device__ float g_ST [NN*(size_t)NN];
__device__ float g_S2T[NN*(size_t)NN];
__device__ __half g_Shi [NN*(size_t)NN];   // S * 1024, fp16 (B side, hi only)
__device__ __half g_SThi[NN*(size_t)NN];   // ST * 1024 hi
__device__ __half g_STlo[NN*(size_t)NN];   // ST * 1024 lo
__device__ __half g_xThi[BB*(size_t)FT*NN];// x^T fp16 (hi only)
__device__ float g_r1[BB*(size_t)NN*FT];
__device__ float g_r2[BB*(size_t)NN*FT];

// ------------------------------ helpers ------------------------------
__device__ __forceinline__ u32 smem_u32(const void* p) {
    u32 a;
    asm("{ .reg .u64 t; cvta.to.shared.u64 t, %1; cvt.u32.u64 %0, t; }" : "=r"(a) : "l"(p));
    return a;
}
__device__ __forceinline__ void cp16(u32 dst, const void* src) {
    asm volatile("cp.async.cg.shared.global [%0], [%1], 16;" :: "r"(dst), "l"(src));
}
#define CP_COMMIT() asm volatile("cp.async.commit_group;" ::: "memory")
#define CP_WAIT(n)  asm volatile("cp.async.wait_group %0;" :: "n"(n) : "memory")

__device__ __forceinline__ void ldsm_x4(u32* r, u32 addr) {
    asm volatile("ldmatrix.sync.aligned.m8n8.x4.shared.b16 {%0,%1,%2,%3}, [%4];"
        : "=r"(r[0]), "=r"(r[1]), "=r"(r[2]), "=r"(r[3]) : "r"(addr));
}
__device__ __forceinline__ void ldsm_x2(u32* r, u32 addr) {
    asm volatile("ldmatrix.sync.aligned.m8n8.x2.shared.b16 {%0,%1}, [%2];"
        : "=r"(r[0]), "=r"(r[1]) : "r"(addr));
}
__device__ __forceinline__ void mma_f16(float* d, const u32* a, const u32* b) {
    asm volatile("mma.sync.aligned.m16n8k16.row.col.f32.f16.f16.f32 "
        "{%0,%1,%2,%3}, {%4,%5,%6,%7}, {%8,%9}, {%0,%1,%2,%3};"
        : "+f"(d[0]), "+f"(d[1]), "+f"(d[2]), "+f"(d[3])
        : "r"(a[0]), "r"(a[1]), "r"(a[2]), "r"(a[3]), "r"(b[0]), "r"(b[1]));
}
__device__ __forceinline__ void split_f16(float v, __half& h, __half& l) {
    h = __float2half_rn(v);
    l = __float2half_rn(v - __half2float(h));
}

// ---------------------------------------------------------------------------
// Kernel 1: S = softmax(relu(E E^T), axis=1); emits S (fp32) and Shi (fp16*1024)
// ---------------------------------------------------------------------------
__global__ __launch_bounds__(256)
void k_supports(const float* __restrict__ E) {
    const int i   = blockIdx.x;
    const int tid = threadIdx.x;
    __shared__ float ei[FIN];
    __shared__ float row[NN];
    __shared__ float red[8];
    __shared__ float bc0, bc1;

    if (tid < FIN) ei[tid] = E[i*FIN + tid];
    __syncthreads();

    float lmax = 0.0f;
    for (int j = tid; j < NN; j += 256) {
        const float4* ej = reinterpret_cast<const float4*>(E + (size_t)j*FIN);
        float dot = 0.f;
        #pragma unroll
        for (int q = 0; q < 4; q++) {
            float4 v = ej[q];
            dot += v.x*ei[q*4+0] + v.y*ei[q*4+1] + v.z*ei[q*4+2] + v.w*ei[q*4+3];
        }
        float r = fmaxf(dot, 0.f);
        row[j] = r;
        lmax = fmaxf(lmax, r);
    }
    #pragma unroll
    for (int o = 16; o > 0; o >>= 1) lmax = fmaxf(lmax, __shfl_xor_sync(0xffffffffu, lmax, o));
    if ((tid & 31) == 0) red[tid >> 5] = lmax;
    __syncthreads();
    if (tid == 0) {
        float m = red[0];
        #pragma unroll
        for (int w = 1; w < 8; w++) m = fmaxf(m, red[w]);
        bc0 = m;
    }
    __syncthreads();
    const float bmax = bc0;

    float lsum = 0.f;
    for (int j = tid; j < NN; j += 256) {
        float e = expf(row[j] - bmax);
        row[j] = e;
        lsum += e;
    }
    #pragma unroll
    for (int o = 16; o > 0; o >>= 1) lsum += __shfl_xor_sync(0xffffffffu, lsum, o);
    if ((tid & 31) == 0) red[tid >> 5] = lsum;
    __syncthreads();
    if (tid == 0) {
        float s = 0.f;
        #pragma unroll
        for (int w = 0; w < 8; w++) s += red[w];
        bc1 = 1.0f / s;
    }
    __syncthreads();
    const float inv = bc1;
    for (int j = tid; j < NN; j += 256) {
        float v = row[j] * inv;
        size_t o = (size_t)i*NN + j;
        g_S[o] = v;
        g_Shi[o] = __float2half_rn(v * 1024.f);
    }
}

// ---------------------------------------------------------------------------
// Kernel 2: ST (fp32) + SThi/STlo (fp16 split of ST*1024)
// ---------------------------------------------------------------------------
__global__ __launch_bounds__(256)
void k_prepS() {
    __shared__ float t[64][65];
    const int tid = threadIdx.x;
    const int i0 = blockIdx.y*64, j0 = blockIdx.x*64;

    for (int idx = tid; idx < 1024; idx += 256) {
        int r = idx >> 4, q = idx & 15;
        float4 v = *reinterpret_cast<const float4*>(&g_S[(size_t)(i0+r)*NN + j0 + q*4]);
        t[r][q*4+0] = v.x; t[r][q*4+1] = v.y; t[r][q*4+2] = v.z; t[r][q*4+3] = v.w;
    }
    __syncthreads();
    for (int idx = tid; idx < 4096; idx += 256) {
        int c = idx >> 6, r = idx & 63;
        float v = t[r][c];
        __half h, l; split_f16(v * 1024.f, h, l);
        size_t o = (size_t)(j0+c)*NN + i0 + r;
        g_ST[o] = v; g_SThi[o] = h; g_STlo[o] = l;
    }
}

// ---------------------------------------------------------------------------
// Kernel 3: xT[b][ft][n] fp16 (hi only)
// ---------------------------------------------------------------------------
__global__ __launch_bounds__(256)
void k_prepx(const float* __restrict__ x) {
    __shared__ float t[FT][33];
    const int tid = threadIdx.x;
    const int b  = blockIdx.y;
    const int n0 = blockIdx.x*32;
    const float* xb = x + (size_t)b*NN*FT;

    for (int idx = tid; idx < 32*48; idx += 256) {
        int r = idx / 48, q = idx % 48;
        float4 v = *reinterpret_cast<const float4*>(&xb[(size_t)(n0+r)*FT + q*4]);
        t[q*4+0][r] = v.x; t[q*4+1][r] = v.y; t[q*4+2][r] = v.z; t[q*4+3][r] = v.w;
    }
    __syncthreads();
    for (int idx = tid; idx < FT*32; idx += 256) {
        int ft = idx >> 5, n = idx & 31;
        size_t o = ((size_t)b*FT + ft)*NN + n0 + n;
        g_xThi[o] = __float2half_rn(t[ft][n]);
    }
}

// ---------------------------------------------------------------------------
// Kernel 4: S2T[i][j] = sum_k ST[i,k]*S[j,k]  (fp16 2-pass, scaled 2^20)
// CTA 128(i) x 256(j), 256 thr, 8 warps (2x4), warp tile 64x64, KC=32.
// Buffers: ATH(128), ATL(128), BH(256) rows, stride 40 halves, double buffered.
// ---------------------------------------------------------------------------
#define S2_BUFH (512*WSTR)      // halves per buffer
#define S2_ATL  (128*WSTR)
#define S2_BH   (256*WSTR)

__global__ __launch_bounds__(256, 1)
void k_s2() {
    extern __shared__ __align__(16) __half sh[];
    const int tid = threadIdx.x, w = tid >> 5, lane = tid & 31;
    const int wm = w >> 2, wn = w & 3;
    const int i0 = blockIdx.y*128, j0 = blockIdx.x*256;
    const u32 sb = smem_u32(sh);

    float d[4][8][4];
    #pragma unroll
    for (int mt = 0; mt < 4; mt++)
        #pragma unroll
        for (int nt = 0; nt < 8; nt++)
            #pragma unroll
            for (int e = 0; e < 4; e++) d[mt][nt][e] = 0.f;

    auto stage = [&](int ch) {
        const int n0 = ch*32;
        const u32 bufb = sb + (u32)((ch & 1) * S2_BUFH * 2);
        #pragma unroll
        for (int idx = tid; idx < 2048; idx += 256) {
            int ru = idx >> 2, q = idx & 3;
            const __half* src;
            int grow, dbase;
            if      (ru < 128) { src = g_SThi; grow = i0 + ru;       dbase = 0; }
            else if (ru < 256) { src = g_STlo; grow = i0 + ru - 128; dbase = S2_ATL; ru -= 128; }
            else               { src = g_Shi;  grow = j0 + ru - 256; dbase = S2_BH;  ru -= 256; }
            u32 dst = bufb + (u32)((dbase + ru*WSTR + q*8)*2);
            cp16(dst, src + (size_t)grow*NN + n0 + q*8);
        }
    };

    stage(0); CP_COMMIT();

    for (int ch = 0; ch < 64; ch++) {
        if (ch < 63) { stage(ch+1); CP_COMMIT(); CP_WAIT(1); }
        else         { CP_WAIT(0); }
        __syncthreads();

        const u32 bufb = sb + (u32)((ch & 1) * S2_BUFH * 2);
        #pragma unroll
        for (int ks = 0; ks < 2; ks++) {
            u32 ah[4][4], bh[8][2];
            const int arow = wm*64 + (lane & 15);
            const int acol = ks*16 + (lane >> 4)*8;
            const int brow = wn*64 + (lane & 7);
            const int bcol = ks*16 + ((lane >> 3) & 1)*8;
            #pragma unroll
            for (int nt = 0; nt < 8; nt++)
                ldsm_x2(bh[nt], bufb + (u32)(((S2_BH + (brow + nt*8)*WSTR) + bcol)*2));
            #pragma unroll
            for (int mt = 0; mt < 4; mt++)
                ldsm_x4(ah[mt], bufb + (u32)((((arow + mt*16)*WSTR) + acol)*2));
            // pass 1: hi * Bhi
            #pragma unroll
            for (int mt = 0; mt < 4; mt++)
                #pragma unroll
                for (int nt = 0; nt < 8; nt++)
                    mma_f16(d[mt][nt], ah[mt], bh[nt]);
            // pass 2: lo * Bhi (reload A regs)
            #pragma unroll
            for (int mt = 0; mt < 4; mt++)
                ldsm_x4(ah[mt], bufb + (u32)(((S2_ATL + (arow + mt*16)*WSTR) + acol)*2));
            #pragma unroll
            for (int mt = 0; mt < 4; mt++)
                #pragma unroll
                for (int nt = 0; nt < 8; nt++)
                    mma_f16(d[mt][nt], ah[mt], bh[nt]);
        }
        __syncthreads();
    }
    const float sc = 1.f / (1024.f*1024.f);   // undo 2^10 * 2^10
    #pragma unroll
    for (int mt = 0; mt < 4; mt++)
        #pragma unroll
        for (int nt = 0; nt < 8; nt++) {
            int row = i0 + wm*64 + mt*16 + (lane >> 2);
            int col = j0 + wn*64 + nt*8 + (lane & 3)*2;
            *reinterpret_cast<float2*>(&g_S2T[(size_t)row*NN + col]) =
                make_float2(d[mt][nt][0]*sc, d[mt][nt][1]*sc);
            *reinterpret_cast<float2*>(&g_S2T[(size_t)(row+8)*NN + col]) =
                make_float2(d[mt][nt][2]*sc, d[mt][nt][3]*sc);
        }
}

// ---------------------------------------------------------------------------
// Kernel 5: masked dual-GEMM, fp16 2-pass, W scaled 2^10 (W2 folds the *2)
//   W rows 0-63 : W1[m,n] = ST[m,n]*A[b,n,m]*1024        -> r1
//   W rows 64-127: W2[m,n] = S2T[m,n]*A[b,n,m]*2048      -> r2
//   B: xT fp16 (full 192 ft rows)
// CTA: 256 thr, M=128, N=192, KC=32, 8 warps (2x4), warp tile 64x48
// ---------------------------------------------------------------------------
#define KM_W(p)    ((p)*10240)               // halves: hi 128*40, lo +5120
#define KM_X(p)    (20480 + (p)*7680)        // halves: 192*40
#define KM_RAWB    71680                     // bytes
#define KM_STB     (KM_RAWB)
#define KM_S2B     (KM_RAWB + 8192)
#define KM_AB      (KM_RAWB + 16384)
#define KM_SMEM    (KM_RAWB + 25088)         // 96768 B

__global__ __launch_bounds__(256, 1)
void k_main(const float* __restrict__ A) {
    extern __shared__ __align__(16) __half sh[];
    char* shc = reinterpret_cast<char*>(sh);
    const int tid = threadIdx.x, w = tid >> 5, lane = tid & 31;
    const int wm = w >> 2, wn = w & 3;
    const int m0 = blockIdx.x*64;
    const int b  = blockIdx.y;
    const u32 sb = smem_u32(sh);

    const float* Ab = A + (size_t)b*NN*NN;
    const __half* xh = g_xThi + (size_t)b*FT*NN;
    float* stST = reinterpret_cast<float*>(shc + KM_STB);
    float* stS2 = reinterpret_cast<float*>(shc + KM_S2B);
    float* As   = reinterpret_cast<float*>(shc + KM_AB);

    float d[4][6][4];
    #pragma unroll
    for (int mt = 0; mt < 4; mt++)
        #pragma unroll
        for (int nt = 0; nt < 6; nt++)
            #pragma unroll
            for (int e = 0; e < 4; e++) d[mt][nt][e] = 0.f;

    auto stage = [&](int ch) {
        const int n0 = ch*32;
        const int p = ch & 1;
        #pragma unroll
        for (int idx = tid; idx < 2304; idx += 256) {
            if (idx < 768) {                 // X: 192 rows x 32 halves
                int row = idx >> 2, q = idx & 3;
                u32 dst = sb + (u32)((KM_X(p) + row*WSTR + q*8)*2);
                cp16(dst, xh + (size_t)row*NN + n0 + q*8);
            } else if (idx < 1792) {         // raw ST/S2T: 2 x 64 rows x 32 f32
                int j = idx - 768;
                int sel = j >> 9;
                int i = j & 511;
                int row = i >> 3, q = i & 7;
                const float* src = sel ? g_S2T : g_ST;
                u32 dst = sb + (u32)((sel ? KM_S2B : KM_STB) + (row*32 + q*4)*4);
                cp16(dst, src + (size_t)(m0+row)*NN + n0 + q*4);
            } else {                         // raw A: 32 rows x 64 f32 (stride 68)
                int j = idx - 1792;
                int row = j >> 4, q = j & 15;
                u32 dst = sb + (u32)(KM_AB + (row*68 + q*4)*4);
                cp16(dst, Ab + (size_t)(n0+row)*NN + m0 + q*4);
            }
        }
    };

    auto build = [&](int ch) {
        const int p = ch & 1;
        #pragma unroll
        for (int idx = tid; idx < 1024; idx += 256) {
            int m = idx >> 4, pp = idx & 15, n = 2*pp;
            float2 st = *reinterpret_cast<const float2*>(&stST[m*32 + n]);
            float2 s2 = *reinterpret_cast<const float2*>(&stS2[m*32 + n]);
            float a0 = As[n*68 + m], a1 = As[(n+1)*68 + m];
            float w1x = st.x*a0*1024.f, w1y = st.y*a1*1024.f;
            float w2x = s2.x*a0*2048.f, w2y = s2.y*a1*2048.f;
            __half h1x,l1x,h1y,l1y,h2x,l2x,h2y,l2y;
            split_f16(w1x,h1x,l1x); split_f16(w1y,h1y,l1y);
            split_f16(w2x,h2x,l2x); split_f16(w2y,h2y,l2y);
            int base = KM_W(p);
            *reinterpret_cast<__half2*>(shc + (base + m*WSTR + n)*2)             = __halves2half2(h1x, h1y);
            *reinterpret_cast<__half2*>(shc + (base + 5120 + m*WSTR + n)*2)      = __halves2half2(l1x, l1y);
            *reinterpret_cast<__half2*>(shc + (base + (64+m)*WSTR + n)*2)        = __halves2half2(h2x, h2y);
            *reinterpret_cast<__half2*>(shc + (base + 5120 + (64+m)*WSTR + n)*2) = __halves2half2(l2x, l2y);
        }
    };

    auto domma = [&](int ch) {
        const int p = ch & 1;
        const u32 wbase = sb + (u32)(KM_W(p)*2);
        const u32 xbase = sb + (u32)(KM_X(p)*2);
        #pragma unroll
        for (int ks = 0; ks < 2; ks++) {
            u32 ah[4][4], bh[6][2];
            const int arow = wm*64 + (lane & 15);
            const int acol = ks*16 + (lane >> 4)*8;
            const int brow = wn*48 + (lane & 7);
            const int bcol = ks*16 + ((lane >> 3) & 1)*8;
            #pragma unroll
            for (int nt = 0; nt < 6; nt++)
                ldsm_x2(bh[nt], xbase + (u32)(((brow + nt*8)*WSTR + bcol)*2));
            #pragma unroll
            for (int mt = 0; mt < 4; mt++)
                ldsm_x4(ah[mt], wbase + (u32)(((arow + mt*16)*WSTR + acol)*2));
            // pass 1: Whi * X
            #pragma unroll
            for (int mt = 0; mt < 4; mt++)
                #pragma unroll
                for (int nt = 0; nt < 6; nt++)
                    mma_f16(d[mt][nt], ah[mt], bh[nt]);
            // pass 2: Wlo * X
            #pragma unroll
            for (int mt = 0; mt < 4; mt++)
                ldsm_x4(ah[mt], wbase + (u32)((5120 + (arow + mt*16)*WSTR + acol)*2));
            #pragma unroll
            for (int mt = 0; mt < 4; mt++)
                #pragma unroll
                for (int nt = 0; nt < 6; nt++)
                    mma_f16(d[mt][nt], ah[mt], bh[nt]);
        }
    };

    stage(0); CP_COMMIT();
    CP_WAIT(0); __syncthreads();
    build(0); __syncthreads();

    for (int c = 0; c < 64; c++) {
        if (c < 63) { stage(c+1); CP_COMMIT(); }
        domma(c);
        if (c < 63) {
            CP_WAIT(0); __syncthreads();
            build(c+1);
            __syncthreads();
        }
    }

    // epilogue: descale by 2^-10 (W scale); W2 already folded the *2
    const float sc = 1.f / 1024.f;
    #pragma unroll
    for (int mt = 0; mt < 4; mt++)
        #pragma unroll
        for (int nt = 0; nt < 6; nt++) {
            int mrow = wm*64 + mt*16 + (lane >> 2);
            int col  = wn*48 + nt*8 + (lane & 3)*2;
            float* base = (mrow < 64) ? g_r1 : g_r2;
            size_t off = ((size_t)b*NN + m0 + (mrow & 63))*FT + col;
            *reinterpret_cast<float2*>(base + off) =
                make_float2(d[mt][nt][0]*sc, d[mt][nt][1]*sc);
            *reinterpret_cast<float2*>(base + off + 8*FT) =
                make_float2(d[mt][nt][2]*sc, d[mt][nt][3]*sc);
        }
}

// ---------------------------------------------------------------------------
// Kernel 6: theta contraction + diagonal identity term + relu
// ---------------------------------------------------------------------------
__global__ __launch_bounds__(256)
void k_theta(const float* __restrict__ x, const float* __restrict__ A,
             const float* __restrict__ theta, float* __restrict__ out) {
    extern __shared__ float smf[];
    float* r1   = smf;
    float* r2   = smf + 6144;
    float* s0   = smf + 12288;
    float* th1  = smf + 18432;
    float* th2  = smf + 18944;
    float* th02 = smf + 19456;

    const int b   = blockIdx.y;
    const int m0  = blockIdx.x * 32;
    const int tid = threadIdx.x;
    const float* xb = x + (size_t)b*NN*FT;
    const float* Ab = A + (size_t)b*NN*NN;

    for (int i = tid; i < 1536; i += 256) {
        reinterpret_cast<float4*>(r1)[i] =
            reinterpret_cast<const float4*>(g_r1 + ((size_t)b*NN + m0)*FT)[i];
        reinterpret_cast<float4*>(r2)[i] =
            reinterpret_cast<const float4*>(g_r2 + ((size_t)b*NN + m0)*FT)[i];
    }
    for (int i = tid; i < FIN*FOUT; i += 256) {
        th1[i] = theta[512 + i];
        float t2 = theta[1024 + i];
        th2[i]  = t2;
        th02[i] = theta[i] - t2;
    }
    for (int i = tid; i < 32*FT; i += 256) {
        int m = i / FT, ftc = i - m*FT;
        float dg = Ab[(size_t)(m0+m)*NN + m0 + m];
        s0[i] = dg * xb[(size_t)(m0+m)*FT + ftc];
    }
    __syncthreads();

    float* outb = out + (size_t)b*NN*FOUT*TT;
    for (int idx = tid; idx < 32*FOUT*TT; idx += 256) {
        int m = idx / (FOUT*TT);
        int r = idx - m*(FOUT*TT);
        int o = r / TT, t = r - o*TT;
        float val = 0.f;
        #pragma unroll
        for (int f = 0; f < FIN; f++) {
            int ft = f*TT + t;
            val = fmaf(r1[m*FT + ft], th1[f*FOUT + o], val);
            val = fmaf(r2[m*FT + ft], th2[f*FOUT + o], val);
            val = fmaf(s0[m*FT + ft], th02[f*FOUT + o], val);
        }
        outb[(size_t)(m0+m)*FOUT*TT + r] = fmaxf(val, 0.f);
    }
}

// ---------------------------------------------------------------------------
extern "C" void kernel_launch(void* const* d_in, const int* in_sizes, int n_in,
                              void* d_out, int out_size) {
    const float *x = nullptr, *A = nullptr, *E = nullptr, *theta = nullptr;
    for (int i = 0; i < n_in; i++) {
        switch (in_sizes[i]) {
            case BB*NN*FIN*TT:   x     = (const float*)d_in[i]; break;
            case BB*NN*NN:       A     = (const float*)d_in[i]; break;
            case NN*FIN:         E     = (const float*)d_in[i]; break;
            case 3*FIN*FOUT:     theta = (const float*)d_in[i]; break;
        }
    }
    float* out = (float*)d_out;

    k_supports<<<NN, 256>>>(E);
    k_prepS<<<dim3(32, 32), 256>>>();
    k_prepx<<<dim3(64, BB), 256>>>(x);

    const int s2_smem = 2 * S2_BUFH * 2;   // 81920 B
    cudaFuncSetAttribute(k_s2, cudaFuncAttributeMaxDynamicSharedMemorySize, s2_smem);
    k_s2<<<dim3(8, 16), 256, s2_smem>>>();

    cudaFuncSetAttribute(k_main, cudaFuncAttributeMaxDynamicSharedMemorySize, KM_SMEM);
    k_main<<<dim3(32, BB), 256, KM_SMEM>>>(A);

    const int smem_th = 19968 * (int)sizeof(float);
    cudaFuncSetAttribute(k_theta, cudaFuncAttributeMaxDynamicSharedMemorySize, smem_th);
    k_theta<<<dim3(NN/32, BB), 256, smem_th>>>(x, A, theta, out);
}

// round 11
// speedup vs baseline: 1.6153x; 1.2561x over previous
#include <cuda_runtime.h>
#include <cuda_fp16.h>
#include <cstdint>

#define NN   2048
#define FIN  16
#define TT   12
#define FOUT 32
#define BB   8
#define FT   192
#define WSTR 40      // padded row stride in halves (80 B, conflict-free ldmatrix)

typedef unsigned int u32;

// ------------------------------ scratch globals ------------------------------
__device__ float g_S  [NN*(size_t)NN];
__device__ float g_ST [NN*(size_t)NN];
__device__ float g_S2T[NN*(size_t)NN];
__device__ __half g_Shi [NN*(size_t)NN];   // S * 1024 fp16
__device__ __half g_SThi[NN*(size_t)NN];   // ST * 1024 fp16
__device__ __half g_xThi[BB*(size_t)FT*NN];// x^T fp16
__device__ float g_r1[BB*(size_t)NN*FT];
__device__ float g_r2[BB*(size_t)NN*FT];

// ------------------------------ helpers ------------------------------
__device__ __forceinline__ u32 smem_u32(const void* p) {
    u32 a;
    asm("{ .reg .u64 t; cvta.to.shared.u64 t, %1; cvt.u32.u64 %0, t; }" : "=r"(a) : "l"(p));
    return a;
}
__device__ __forceinline__ void cp16(u32 dst, const void* src) {
    asm volatile("cp.async.cg.shared.global [%0], [%1], 16;" :: "r"(dst), "l"(src));
}
#define CP_COMMIT() asm volatile("cp.async.commit_group;" ::: "memory")
#define CP_WAIT(n)  asm volatile("cp.async.wait_group %0;" :: "n"(n) : "memory")

__device__ __forceinline__ void ldsm_x4(u32* r, u32 addr) {
    asm volatile("ldmatrix.sync.aligned.m8n8.x4.shared.b16 {%0,%1,%2,%3}, [%4];"
        : "=r"(r[0]), "=r"(r[1]), "=r"(r[2]), "=r"(r[3]) : "r"(addr));
}
__device__ __forceinline__ void ldsm_x2(u32* r, u32 addr) {
    asm volatile("ldmatrix.sync.aligned.m8n8.x2.shared.b16 {%0,%1}, [%2];"
        : "=r"(r[0]), "=r"(r[1]) : "r"(addr));
}
__device__ __forceinline__ void mma_f16(float* d, const u32* a, const u32* b) {
    asm volatile("mma.sync.aligned.m16n8k16.row.col.f32.f16.f16.f32 "
        "{%0,%1,%2,%3}, {%4,%5,%6,%7}, {%8,%9}, {%0,%1,%2,%3};"
        : "+f"(d[0]), "+f"(d[1]), "+f"(d[2]), "+f"(d[3])
        : "r"(a[0]), "r"(a[1]), "r"(a[2]), "r"(a[3]), "r"(b[0]), "r"(b[1]));
}

// ---------------------------------------------------------------------------
// Kernel 1: S = softmax(relu(E E^T), axis=1); 8 rows per block (E-reuse)
// emits S (fp32) and Shi (fp16 * 1024)
// ---------------------------------------------------------------------------
__global__ __launch_bounds__(256)
void k_supports(const float* __restrict__ E) {
    extern __shared__ float sms[];
    float* rows = sms;              // 8*2048
    float* e8   = sms + 8*NN;       // 128
    float* pr   = e8 + 128;         // 8*256
    __shared__ float bc[8];

    const int i0  = blockIdx.x * 8;
    const int tid = threadIdx.x;
    const int w   = tid >> 5, lane = tid & 31;

    if (tid < 128) e8[tid] = E[(i0 + (tid >> 4))*FIN + (tid & 15)];
    __syncthreads();

    float lv[8];
    #pragma unroll
    for (int r = 0; r < 8; r++) lv[r] = 0.f;

    for (int j = tid; j < NN; j += 256) {
        float ej[16];
        const float4* p4 = reinterpret_cast<const float4*>(E + (size_t)j*FIN);
        #pragma unroll
        for (int q = 0; q < 4; q++) {
            float4 v = p4[q];
            ej[q*4+0] = v.x; ej[q*4+1] = v.y; ej[q*4+2] = v.z; ej[q*4+3] = v.w;
        }
        #pragma unroll
        for (int r = 0; r < 8; r++) {
            float dot = 0.f;
            #pragma unroll
            for (int q = 0; q < 16; q++) dot = fmaf(ej[q], e8[r*16+q], dot);
            float rv = fmaxf(dot, 0.f);
            rows[r*NN + j] = rv;
            lv[r] = fmaxf(lv[r], rv);
        }
    }
    // block max per row: warp w reduces row w
    #pragma unroll
    for (int r = 0; r < 8; r++) pr[r*256 + tid] = lv[r];
    __syncthreads();
    {
        float m = pr[w*256 + lane];
        #pragma unroll
        for (int o = 1; o < 8; o++) m = fmaxf(m, pr[w*256 + o*32 + lane]);
        #pragma unroll
        for (int o = 16; o > 0; o >>= 1) m = fmaxf(m, __shfl_xor_sync(0xffffffffu, m, o));
        if (lane == 0) bc[w] = m;
    }
    __syncthreads();
    float bmax[8];
    #pragma unroll
    for (int r = 0; r < 8; r++) { bmax[r] = bc[r]; lv[r] = 0.f; }
    __syncthreads();

    for (int j = tid; j < NN; j += 256)
        #pragma unroll
        for (int r = 0; r < 8; r++) {
            float e = expf(rows[r*NN + j] - bmax[r]);
            rows[r*NN + j] = e;
            lv[r] += e;
        }
    #pragma unroll
    for (int r = 0; r < 8; r++) pr[r*256 + tid] = lv[r];
    __syncthreads();
    {
        float s = pr[w*256 + lane];
        #pragma unroll
        for (int o = 1; o < 8; o++) s += pr[w*256 + o*32 + lane];
        #pragma unroll
        for (int o = 16; o > 0; o >>= 1) s += __shfl_xor_sync(0xffffffffu, s, o);
        if (lane == 0) bc[w] = 1.0f / s;
    }
    __syncthreads();
    float inv[8];
    #pragma unroll
    for (int r = 0; r < 8; r++) inv[r] = bc[r];

    for (int j = tid; j < NN; j += 256)
        #pragma unroll
        for (int r = 0; r < 8; r++) {
            float v = rows[r*NN + j] * inv[r];
            size_t o = (size_t)(i0 + r)*NN + j;
            g_S[o]   = v;
            g_Shi[o] = __float2half_rn(v * 1024.f);
        }
}

// ---------------------------------------------------------------------------
// Kernel 2: ST (fp32) + SThi (fp16 of ST*1024)
// ---------------------------------------------------------------------------
__global__ __launch_bounds__(256)
void k_prepS() {
    __shared__ float t[64][65];
    const int tid = threadIdx.x;
    const int i0 = blockIdx.y*64, j0 = blockIdx.x*64;

    for (int idx = tid; idx < 1024; idx += 256) {
        int r = idx >> 4, q = idx & 15;
        float4 v = *reinterpret_cast<const float4*>(&g_S[(size_t)(i0+r)*NN + j0 + q*4]);
        t[r][q*4+0] = v.x; t[r][q*4+1] = v.y; t[r][q*4+2] = v.z; t[r][q*4+3] = v.w;
    }
    __syncthreads();
    for (int idx = tid; idx < 4096; idx += 256) {
        int c = idx >> 6, r = idx & 63;
        float v = t[r][c];
        size_t o = (size_t)(j0+c)*NN + i0 + r;
        g_ST[o] = v;
        g_SThi[o] = __float2half_rn(v * 1024.f);
    }
}

// ---------------------------------------------------------------------------
// Kernel 3: xT[b][ft][n] fp16
// ---------------------------------------------------------------------------
__global__ __launch_bounds__(256)
void k_prepx(const float* __restrict__ x) {
    __shared__ float t[FT][33];
    const int tid = threadIdx.x;
    const int b  = blockIdx.y;
    const int n0 = blockIdx.x*32;
    const float* xb = x + (size_t)b*NN*FT;

    for (int idx = tid; idx < 32*48; idx += 256) {
        int r = idx / 48, q = idx % 48;
        float4 v = *reinterpret_cast<const float4*>(&xb[(size_t)(n0+r)*FT + q*4]);
        t[q*4+0][r] = v.x; t[q*4+1][r] = v.y; t[q*4+2][r] = v.z; t[q*4+3][r] = v.w;
    }
    __syncthreads();
    for (int idx = tid; idx < FT*32; idx += 256) {
        int ft = idx >> 5, n = idx & 31;
        size_t o = ((size_t)b*FT + ft)*NN + n0 + n;
        g_xThi[o] = __float2half_rn(t[ft][n]);
    }
}

// ---------------------------------------------------------------------------
// Kernel 4: S2T[i][j] = sum_k ST[i,k]*S[j,k]  (fp16 single-pass, scaled 2^20)
// CTA 128(i) x 256(j), 256 thr, 8 warps (2x4), warp tile 64x64, KC=32.
// Buffers: ATH(128 rows) + BH(256 rows), stride 40 halves, double buffered.
// ---------------------------------------------------------------------------
#define S2_BUFH (384*WSTR)      // halves per buffer
#define S2_BH   (128*WSTR)

__global__ __launch_bounds__(256, 1)
void k_s2() {
    extern __shared__ __align__(16) __half sh[];
    const int tid = threadIdx.x, w = tid >> 5, lane = tid & 31;
    const int wm = w >> 2, wn = w & 3;
    const int i0 = blockIdx.y*128, j0 = blockIdx.x*256;
    const u32 sb = smem_u32(sh);

    float d[4][8][4];
    #pragma unroll
    for (int mt = 0; mt < 4; mt++)
        #pragma unroll
        for (int nt = 0; nt < 8; nt++)
            #pragma unroll
            for (int e = 0; e < 4; e++) d[mt][nt][e] = 0.f;

    auto stage = [&](int ch) {
        const int n0 = ch*32;
        const u32 bufb = sb + (u32)((ch & 1) * S2_BUFH * 2);
        #pragma unroll
        for (int idx = tid; idx < 1536; idx += 256) {
            int ru = idx >> 2, q = idx & 3;
            const __half* src;
            int grow, dbase;
            if (ru < 128) { src = g_SThi; grow = i0 + ru;       dbase = 0; }
            else          { src = g_Shi;  grow = j0 + ru - 128; dbase = S2_BH; ru -= 128; }
            u32 dst = bufb + (u32)((dbase + ru*WSTR + q*8)*2);
            cp16(dst, src + (size_t)grow*NN + n0 + q*8);
        }
    };

    stage(0); CP_COMMIT();

    for (int ch = 0; ch < 64; ch++) {
        if (ch < 63) { stage(ch+1); CP_COMMIT(); CP_WAIT(1); }
        else         { CP_WAIT(0); }
        __syncthreads();

        const u32 bufb = sb + (u32)((ch & 1) * S2_BUFH * 2);
        #pragma unroll
        for (int ks = 0; ks < 2; ks++) {
            u32 ah[4][4], bh[8][2];
            const int arow = wm*64 + (lane & 15);
            const int acol = ks*16 + (lane >> 4)*8;
            const int brow = wn*64 + (lane & 7);
            const int bcol = ks*16 + ((lane >> 3) & 1)*8;
            #pragma unroll
            for (int nt = 0; nt < 8; nt++)
                ldsm_x2(bh[nt], bufb + (u32)(((S2_BH + (brow + nt*8)*WSTR) + bcol)*2));
            #pragma unroll
            for (int mt = 0; mt < 4; mt++)
                ldsm_x4(ah[mt], bufb + (u32)((((arow + mt*16)*WSTR) + acol)*2));
            #pragma unroll
            for (int mt = 0; mt < 4; mt++)
                #pragma unroll
                for (int nt = 0; nt < 8; nt++)
                    mma_f16(d[mt][nt], ah[mt], bh[nt]);
        }
        __syncthreads();
    }
    const float sc = 1.f / (1024.f*1024.f);
    #pragma unroll
    for (int mt = 0; mt < 4; mt++)
        #pragma unroll
        for (int nt = 0; nt < 8; nt++) {
            int row = i0 + wm*64 + mt*16 + (lane >> 2);
            int col = j0 + wn*64 + nt*8 + (lane & 3)*2;
            *reinterpret_cast<float2*>(&g_S2T[(size_t)row*NN + col]) =
                make_float2(d[mt][nt][0]*sc, d[mt][nt][1]*sc);
            *reinterpret_cast<float2*>(&g_S2T[(size_t)(row+8)*NN + col]) =
                make_float2(d[mt][nt][2]*sc, d[mt][nt][3]*sc);
        }
}

// ---------------------------------------------------------------------------
// Kernel 5: masked dual-GEMM, fp16 single-pass, W scaled 2^10 (W2 folds *2)
//   W rows 0-63 : W1 = ST*A*1024  -> r1;  rows 64-127: W2 = S2T*A*2048 -> r2
// CTA: 256 thr, M=128, N=192, KC=32, 8 warps (2x4), warp tile 64x48
// ---------------------------------------------------------------------------
#define KM_W(p)    ((p)*5120)                // halves: 128*40
#define KM_X(p)    (10240 + (p)*7680)        // halves: 192*40
#define KM_RAWB    51200                     // bytes
#define KM_STB     (KM_RAWB)
#define KM_S2B     (KM_RAWB + 8192)
#define KM_AB      (KM_RAWB + 16384)
#define KM_SMEM    (KM_RAWB + 25088)         // 76288 B

__global__ __launch_bounds__(256, 1)
void k_main(const float* __restrict__ A) {
    extern __shared__ __align__(16) __half sh[];
    char* shc = reinterpret_cast<char*>(sh);
    const int tid = threadIdx.x, w = tid >> 5, lane = tid & 31;
    const int wm = w >> 2, wn = w & 3;
    const int m0 = blockIdx.x*64;
    const int b  = blockIdx.y;
    const u32 sb = smem_u32(sh);

    const float* Ab = A + (size_t)b*NN*NN;
    const __half* xh = g_xThi + (size_t)b*FT*NN;
    float* stST = reinterpret_cast<float*>(shc + KM_STB);
    float* stS2 = reinterpret_cast<float*>(shc + KM_S2B);
    float* As   = reinterpret_cast<float*>(shc + KM_AB);

    float d[4][6][4];
    #pragma unroll
    for (int mt = 0; mt < 4; mt++)
        #pragma unroll
        for (int nt = 0; nt < 6; nt++)
            #pragma unroll
            for (int e = 0; e < 4; e++) d[mt][nt][e] = 0.f;

    auto stage = [&](int ch) {
        const int n0 = ch*32;
        const int p = ch & 1;
        #pragma unroll
        for (int idx = tid; idx < 2304; idx += 256) {
            if (idx < 768) {                 // X: 192 rows x 32 halves
                int row = idx >> 2, q = idx & 3;
                u32 dst = sb + (u32)((KM_X(p) + row*WSTR + q*8)*2);
                cp16(dst, xh + (size_t)row*NN + n0 + q*8);
            } else if (idx < 1792) {         // raw ST/S2T: 2 x 64 rows x 32 f32
                int j = idx - 768;
                int sel = j >> 9;
                int i = j & 511;
                int row = i >> 3, q = i & 7;
                const float* src = sel ? g_S2T : g_ST;
                u32 dst = sb + (u32)((sel ? KM_S2B : KM_STB) + (row*32 + q*4)*4);
                cp16(dst, src + (size_t)(m0+row)*NN + n0 + q*4);
            } else {                         // raw A: 32 rows x 64 f32 (stride 68)
                int j = idx - 1792;
                int row = j >> 4, q = j & 15;
                u32 dst = sb + (u32)(KM_AB + (row*68 + q*4)*4);
                cp16(dst, Ab + (size_t)(n0+row)*NN + m0 + q*4);
            }
        }
    };

    auto build = [&](int ch) {
        const int p = ch & 1;
        #pragma unroll
        for (int idx = tid; idx < 1024; idx += 256) {
            int m = idx >> 4, pp = idx & 15, n = 2*pp;
            float2 st = *reinterpret_cast<const float2*>(&stST[m*32 + n]);
            float2 s2 = *reinterpret_cast<const float2*>(&stS2[m*32 + n]);
            float a0 = As[n*68 + m], a1 = As[(n+1)*68 + m];
            __half h1x = __float2half_rn(st.x*a0*1024.f);
            __half h1y = __float2half_rn(st.y*a1*1024.f);
            __half h2x = __float2half_rn(s2.x*a0*2048.f);
            __half h2y = __float2half_rn(s2.y*a1*2048.f);
            int base = KM_W(p);
            *reinterpret_cast<__half2*>(shc + (base + m*WSTR + n)*2)      = __halves2half2(h1x, h1y);
            *reinterpret_cast<__half2*>(shc + (base + (64+m)*WSTR + n)*2) = __halves2half2(h2x, h2y);
        }
    };

    auto domma = [&](int ch) {
        const int p = ch & 1;
        const u32 wbase = sb + (u32)(KM_W(p)*2);
        const u32 xbase = sb + (u32)(KM_X(p)*2);
        #pragma unroll
        for (int ks = 0; ks < 2; ks++) {
            u32 ah[4][4], bh[6][2];
            const int arow = wm*64 + (lane & 15);
            const int acol = ks*16 + (lane >> 4)*8;
            const int brow = wn*48 + (lane & 7);
            const int bcol = ks*16 + ((lane >> 3) & 1)*8;
            #pragma unroll
            for (int nt = 0; nt < 6; nt++)
                ldsm_x2(bh[nt], xbase + (u32)(((brow + nt*8)*WSTR + bcol)*2));
            #pragma unroll
            for (int mt = 0; mt < 4; mt++)
                ldsm_x4(ah[mt], wbase + (u32)(((arow + mt*16)*WSTR + acol)*2));
            #pragma unroll
            for (int mt = 0; mt < 4; mt++)
                #pragma unroll
                for (int nt = 0; nt < 6; nt++)
                    mma_f16(d[mt][nt], ah[mt], bh[nt]);
        }
    };

    stage(0); CP_COMMIT();
    CP_WAIT(0); __syncthreads();
    build(0); __syncthreads();

    for (int c = 0; c < 64; c++) {
        if (c < 63) { stage(c+1); CP_COMMIT(); }
        domma(c);
        if (c < 63) {
            CP_WAIT(0); __syncthreads();
            build(c+1);
            __syncthreads();
        }
    }

    const float sc = 1.f / 1024.f;
    #pragma unroll
    for (int mt = 0; mt < 4; mt++)
        #pragma unroll
        for (int nt = 0; nt < 6; nt++) {
            int mrow = wm*64 + mt*16 + (lane >> 2);
            int col  = wn*48 + nt*8 + (lane & 3)*2;
            float* base = (mrow < 64) ? g_r1 : g_r2;
            size_t off = ((size_t)b*NN + m0 + (mrow & 63))*FT + col;
            *reinterpret_cast<float2*>(base + off) =
                make_float2(d[mt][nt][0]*sc, d[mt][nt][1]*sc);
            *reinterpret_cast<float2*>(base + off + 8*FT) =
                make_float2(d[mt][nt][2]*sc, d[mt][nt][3]*sc);
        }
}

// ---------------------------------------------------------------------------
// Kernel 6: theta contraction + diagonal identity term + relu
// ---------------------------------------------------------------------------
__global__ __launch_bounds__(256)
void k_theta(const float* __restrict__ x, const float* __restrict__ A,
             const float* __restrict__ theta, float* __restrict__ out) {
    extern __shared__ float smf[];
    float* r1   = smf;
    float* r2   = smf + 6144;
    float* s0   = smf + 12288;
    float* th1  = smf + 18432;
    float* th2  = smf + 18944;
    float* th02 = smf + 19456;

    const int b   = blockIdx.y;
    const int m0  = blockIdx.x * 32;
    const int tid = threadIdx.x;
    const float* xb = x + (size_t)b*NN*FT;
    const float* Ab = A + (size_t)b*NN*NN;

    for (int i = tid; i < 1536; i += 256) {
        reinterpret_cast<float4*>(r1)[i] =
            reinterpret_cast<const float4*>(g_r1 + ((size_t)b*NN + m0)*FT)[i];
        reinterpret_cast<float4*>(r2)[i] =
            reinterpret_cast<const float4*>(g_r2 + ((size_t)b*NN + m0)*FT)[i];
    }
    for (int i = tid; i < FIN*FOUT; i += 256) {
        th1[i] = theta[512 + i];
        float t2 = theta[1024 + i];
        th2[i]  = t2;
        th02[i] = theta[i] - t2;
    }
    for (int i = tid; i < 32*FT; i += 256) {
        int m = i / FT, ftc = i - m*FT;
        float dg = Ab[(size_t)(m0+m)*NN + m0 + m];
        s0[i] = dg * xb[(size_t)(m0+m)*FT + ftc];
    }
    __syncthreads();

    float* outb = out + (size_t)b*NN*FOUT*TT;
    for (int idx = tid; idx < 32*FOUT*TT; idx += 256) {
        int m = idx / (FOUT*TT);
        int r = idx - m*(FOUT*TT);
        int o = r / TT, t = r - o*TT;
        float val = 0.f;
        #pragma unroll
        for (int f = 0; f < FIN; f++) {
            int ft = f*TT + t;
            val = fmaf(r1[m*FT + ft], th1[f*FOUT + o], val);
            val = fmaf(r2[m*FT + ft], th2[f*FOUT + o], val);
            val = fmaf(s0[m*FT + ft], th02[f*FOUT + o], val);
        }
        outb[(size_t)(m0+m)*FOUT*TT + r] = fmaxf(val, 0.f);
    }
}

// ---------------------------------------------------------------------------
extern "C" void kernel_launch(void* const* d_in, const int* in_sizes, int n_in,
                              void* d_out, int out_size) {
    const float *x = nullptr, *A = nullptr, *E = nullptr, *theta = nullptr;
    for (int i = 0; i < n_in; i++) {
        switch (in_sizes[i]) {
            case BB*NN*FIN*TT:   x     = (const float*)d_in[i]; break;
            case BB*NN*NN:       A     = (const float*)d_in[i]; break;
            case NN*FIN:         E     = (const float*)d_in[i]; break;
            case 3*FIN*FOUT:     theta = (const float*)d_in[i]; break;
        }
    }
    float* out = (float*)d_out;

    const int sup_smem = (8*NN + 128 + 8*256) * (int)sizeof(float);  // ~74 KB
    cudaFuncSetAttribute(k_supports, cudaFuncAttributeMaxDynamicSharedMemorySize, sup_smem);
    k_supports<<<NN/8, 256, sup_smem>>>(E);

    k_prepS<<<dim3(32, 32), 256>>>();
    k_prepx<<<dim3(64, BB), 256>>>(x);

    const int s2_smem = 2 * S2_BUFH * 2;   // 61440 B
    cudaFuncSetAttribute(k_s2, cudaFuncAttributeMaxDynamicSharedMemorySize, s2_smem);
    k_s2<<<dim3(8, 16), 256, s2_smem>>>();

    cudaFuncSetAttribute(k_main, cudaFuncAttributeMaxDynamicSharedMemorySize, KM_SMEM);
    k_main<<<dim3(32, BB), 256, KM_SMEM>>>(A);

    const int smem_th = 19968 * (int)sizeof(float);
    cudaFuncSetAttribute(k_theta, cudaFuncAttributeMaxDynamicSharedMemorySize, smem_th);
    k_theta<<<dim3(NN/32, BB), 256, smem_th>>>(x, A, theta, out);
}

// round 12
// speedup vs baseline: 2.0152x; 1.2476x over previous
#include <cuda_runtime.h>
#include <cuda_fp16.h>
#include <cstdint>

#define NN   2048
#define FIN  16
#define TT   12
#define FOUT 32
#define BB   8
#define FT   192
#define WSTR 40      // k_main padded row stride in halves (80 B)
#define S2STR 72     // k_s2 padded row stride in halves (144 B), KC=64

typedef unsigned int u32;

// ------------------------------ scratch globals ------------------------------
__device__ float g_S  [NN*(size_t)NN];
__device__ float g_ST [NN*(size_t)NN];
__device__ float g_S2T[NN*(size_t)NN];
__device__ __half g_Shi [NN*(size_t)NN];   // S * 1024 fp16
__device__ __half g_SThi[NN*(size_t)NN];   // ST * 1024 fp16
__device__ __half g_xThi[BB*(size_t)FT*NN];// x^T fp16
__device__ float g_r1[BB*(size_t)NN*FT];
__device__ float g_r2[BB*(size_t)NN*FT];

// ------------------------------ helpers ------------------------------
__device__ __forceinline__ u32 smem_u32(const void* p) {
    u32 a;
    asm("{ .reg .u64 t; cvta.to.shared.u64 t, %1; cvt.u32.u64 %0, t; }" : "=r"(a) : "l"(p));
    return a;
}
__device__ __forceinline__ void cp16(u32 dst, const void* src) {
    asm volatile("cp.async.cg.shared.global [%0], [%1], 16;" :: "r"(dst), "l"(src));
}
#define CP_COMMIT() asm volatile("cp.async.commit_group;" ::: "memory")
#define CP_WAIT(n)  asm volatile("cp.async.wait_group %0;" :: "n"(n) : "memory")

__device__ __forceinline__ void ldsm_x4(u32* r, u32 addr) {
    asm volatile("ldmatrix.sync.aligned.m8n8.x4.shared.b16 {%0,%1,%2,%3}, [%4];"
        : "=r"(r[0]), "=r"(r[1]), "=r"(r[2]), "=r"(r[3]) : "r"(addr));
}
__device__ __forceinline__ void ldsm_x2(u32* r, u32 addr) {
    asm volatile("ldmatrix.sync.aligned.m8n8.x2.shared.b16 {%0,%1}, [%2];"
        : "=r"(r[0]), "=r"(r[1]) : "r"(addr));
}
__device__ __forceinline__ void mma_f16(float* d, const u32* a, const u32* b) {
    asm volatile("mma.sync.aligned.m16n8k16.row.col.f32.f16.f16.f32 "
        "{%0,%1,%2,%3}, {%4,%5,%6,%7}, {%8,%9}, {%0,%1,%2,%3};"
        : "+f"(d[0]), "+f"(d[1]), "+f"(d[2]), "+f"(d[3])
        : "r"(a[0]), "r"(a[1]), "r"(a[2]), "r"(a[3]), "r"(b[0]), "r"(b[1]));
}

// ---------------------------------------------------------------------------
// Kernel 1: S = softmax(relu(E E^T), axis=1); 8 rows per block
// ---------------------------------------------------------------------------
__global__ __launch_bounds__(256)
void k_supports(const float* __restrict__ E) {
    extern __shared__ float sms[];
    float* rows = sms;              // 8*2048
    float* e8   = sms + 8*NN;       // 128
    float* pr   = e8 + 128;         // 8*256
    __shared__ float bc[8];

    const int i0  = blockIdx.x * 8;
    const int tid = threadIdx.x;
    const int w   = tid >> 5, lane = tid & 31;

    if (tid < 128) e8[tid] = E[(i0 + (tid >> 4))*FIN + (tid & 15)];
    __syncthreads();

    float lv[8];
    #pragma unroll
    for (int r = 0; r < 8; r++) lv[r] = 0.f;

    for (int j = tid; j < NN; j += 256) {
        float ej[16];
        const float4* p4 = reinterpret_cast<const float4*>(E + (size_t)j*FIN);
        #pragma unroll
        for (int q = 0; q < 4; q++) {
            float4 v = p4[q];
            ej[q*4+0] = v.x; ej[q*4+1] = v.y; ej[q*4+2] = v.z; ej[q*4+3] = v.w;
        }
        #pragma unroll
        for (int r = 0; r < 8; r++) {
            float dot = 0.f;
            #pragma unroll
            for (int q = 0; q < 16; q++) dot = fmaf(ej[q], e8[r*16+q], dot);
            float rv = fmaxf(dot, 0.f);
            rows[r*NN + j] = rv;
            lv[r] = fmaxf(lv[r], rv);
        }
    }
    #pragma unroll
    for (int r = 0; r < 8; r++) pr[r*256 + tid] = lv[r];
    __syncthreads();
    {
        float m = pr[w*256 + lane];
        #pragma unroll
        for (int o = 1; o < 8; o++) m = fmaxf(m, pr[w*256 + o*32 + lane]);
        #pragma unroll
        for (int o = 16; o > 0; o >>= 1) m = fmaxf(m, __shfl_xor_sync(0xffffffffu, m, o));
        if (lane == 0) bc[w] = m;
    }
    __syncthreads();
    float bmax[8];
    #pragma unroll
    for (int r = 0; r < 8; r++) { bmax[r] = bc[r]; lv[r] = 0.f; }
    __syncthreads();

    for (int j = tid; j < NN; j += 256)
        #pragma unroll
        for (int r = 0; r < 8; r++) {
            float e = expf(rows[r*NN + j] - bmax[r]);
            rows[r*NN + j] = e;
            lv[r] += e;
        }
    #pragma unroll
    for (int r = 0; r < 8; r++) pr[r*256 + tid] = lv[r];
    __syncthreads();
    {
        float s = pr[w*256 + lane];
        #pragma unroll
        for (int o = 1; o < 8; o++) s += pr[w*256 + o*32 + lane];
        #pragma unroll
        for (int o = 16; o > 0; o >>= 1) s += __shfl_xor_sync(0xffffffffu, s, o);
        if (lane == 0) bc[w] = 1.0f / s;
    }
    __syncthreads();
    float inv[8];
    #pragma unroll
    for (int r = 0; r < 8; r++) inv[r] = bc[r];

    for (int j = tid; j < NN; j += 256)
        #pragma unroll
        for (int r = 0; r < 8; r++) {
            float v = rows[r*NN + j] * inv[r];
            size_t o = (size_t)(i0 + r)*NN + j;
            g_S[o]   = v;
            g_Shi[o] = __float2half_rn(v * 1024.f);
        }
}

// ---------------------------------------------------------------------------
// Kernel 2: ST (fp32) + SThi (fp16 of ST*1024)
// ---------------------------------------------------------------------------
__global__ __launch_bounds__(256)
void k_prepS() {
    __shared__ float t[64][65];
    const int tid = threadIdx.x;
    const int i0 = blockIdx.y*64, j0 = blockIdx.x*64;

    for (int idx = tid; idx < 1024; idx += 256) {
        int r = idx >> 4, q = idx & 15;
        float4 v = *reinterpret_cast<const float4*>(&g_S[(size_t)(i0+r)*NN + j0 + q*4]);
        t[r][q*4+0] = v.x; t[r][q*4+1] = v.y; t[r][q*4+2] = v.z; t[r][q*4+3] = v.w;
    }
    __syncthreads();
    for (int idx = tid; idx < 4096; idx += 256) {
        int c = idx >> 6, r = idx & 63;
        float v = t[r][c];
        size_t o = (size_t)(j0+c)*NN + i0 + r;
        g_ST[o] = v;
        g_SThi[o] = __float2half_rn(v * 1024.f);
    }
}

// ---------------------------------------------------------------------------
// Kernel 3: xT[b][ft][n] fp16
// ---------------------------------------------------------------------------
__global__ __launch_bounds__(256)
void k_prepx(const float* __restrict__ x) {
    __shared__ float t[FT][33];
    const int tid = threadIdx.x;
    const int b  = blockIdx.y;
    const int n0 = blockIdx.x*32;
    const float* xb = x + (size_t)b*NN*FT;

    for (int idx = tid; idx < 32*48; idx += 256) {
        int r = idx / 48, q = idx % 48;
        float4 v = *reinterpret_cast<const float4*>(&xb[(size_t)(n0+r)*FT + q*4]);
        t[q*4+0][r] = v.x; t[q*4+1][r] = v.y; t[q*4+2][r] = v.z; t[q*4+3][r] = v.w;
    }
    __syncthreads();
    for (int idx = tid; idx < FT*32; idx += 256) {
        int ft = idx >> 5, n = idx & 31;
        size_t o = ((size_t)b*FT + ft)*NN + n0 + n;
        g_xThi[o] = __float2half_rn(t[ft][n]);
    }
}

// ---------------------------------------------------------------------------
// Kernel 4: S2T[i][j] = sum_k ST[i,k]*S[j,k]  (fp16 single-pass, scaled 2^20)
// CTA 128(i) x 256(j), 256 thr, 8 warps (2x4), warp tile 64x64, KC=64.
// 32 chunks, 4 ks-steps between barriers, cp.async double buffered.
// ---------------------------------------------------------------------------
#define S2_BUFH (384*S2STR)     // halves per buffer
#define S2_BH   (128*S2STR)

__global__ __launch_bounds__(256, 1)
void k_s2() {
    extern __shared__ __align__(16) __half sh[];
    const int tid = threadIdx.x, w = tid >> 5, lane = tid & 31;
    const int wm = w >> 2, wn = w & 3;
    const int i0 = blockIdx.y*128, j0 = blockIdx.x*256;
    const u32 sb = smem_u32(sh);

    float d[4][8][4];
    #pragma unroll
    for (int mt = 0; mt < 4; mt++)
        #pragma unroll
        for (int nt = 0; nt < 8; nt++)
            #pragma unroll
            for (int e = 0; e < 4; e++) d[mt][nt][e] = 0.f;

    auto stage = [&](int ch) {
        const int n0 = ch*64;
        const u32 bufb = sb + (u32)((ch & 1) * S2_BUFH * 2);
        #pragma unroll
        for (int idx = tid; idx < 3072; idx += 256) {
            int ru = idx >> 3, q = idx & 7;
            const __half* src;
            int grow, dbase;
            if (ru < 128) { src = g_SThi; grow = i0 + ru;       dbase = 0; }
            else          { src = g_Shi;  grow = j0 + ru - 128; dbase = S2_BH; ru -= 128; }
            u32 dst = bufb + (u32)((dbase + ru*S2STR + q*8)*2);
            cp16(dst, src + (size_t)grow*NN + n0 + q*8);
        }
    };

    stage(0); CP_COMMIT();

    for (int ch = 0; ch < 32; ch++) {
        if (ch < 31) { stage(ch+1); CP_COMMIT(); CP_WAIT(1); }
        else         { CP_WAIT(0); }
        __syncthreads();

        const u32 bufb = sb + (u32)((ch & 1) * S2_BUFH * 2);
        #pragma unroll
        for (int ks = 0; ks < 4; ks++) {
            u32 ah[4][4], bh[8][2];
            const int arow = wm*64 + (lane & 15);
            const int acol = ks*16 + (lane >> 4)*8;
            const int brow = wn*64 + (lane & 7);
            const int bcol = ks*16 + ((lane >> 3) & 1)*8;
            #pragma unroll
            for (int nt = 0; nt < 8; nt++)
                ldsm_x2(bh[nt], bufb + (u32)(((S2_BH + (brow + nt*8)*S2STR) + bcol)*2));
            #pragma unroll
            for (int mt = 0; mt < 4; mt++)
                ldsm_x4(ah[mt], bufb + (u32)((((arow + mt*16)*S2STR) + acol)*2));
            #pragma unroll
            for (int mt = 0; mt < 4; mt++)
                #pragma unroll
                for (int nt = 0; nt < 8; nt++)
                    mma_f16(d[mt][nt], ah[mt], bh[nt]);
        }
        __syncthreads();
    }
    const float sc = 1.f / (1024.f*1024.f);
    #pragma unroll
    for (int mt = 0; mt < 4; mt++)
        #pragma unroll
        for (int nt = 0; nt < 8; nt++) {
            int row = i0 + wm*64 + mt*16 + (lane >> 2);
            int col = j0 + wn*64 + nt*8 + (lane & 3)*2;
            *reinterpret_cast<float2*>(&g_S2T[(size_t)row*NN + col]) =
                make_float2(d[mt][nt][0]*sc, d[mt][nt][1]*sc);
            *reinterpret_cast<float2*>(&g_S2T[(size_t)(row+8)*NN + col]) =
                make_float2(d[mt][nt][2]*sc, d[mt][nt][3]*sc);
        }
}

// ---------------------------------------------------------------------------
// Kernel 5: masked dual-GEMM, fp16 single-pass, 2 CTAs/SM (one wave)
//   W rows 0-63 : W1 = ST*A*1024  -> r1;  rows 64-127: W2 = S2T*A*2048 -> r2
// CTA: 256 thr, M=128, N=192, KC=32, 8 warps (2x4), warp tile 64x48
// ---------------------------------------------------------------------------
#define KM_W(p)    ((p)*5120)                // halves: 128*40
#define KM_X(p)    (10240 + (p)*7680)        // halves: 192*40
#define KM_RAWB    51200                     // bytes
#define KM_STB     (KM_RAWB)
#define KM_S2B     (KM_RAWB + 8192)
#define KM_AB      (KM_RAWB + 16384)
#define KM_SMEM    (KM_RAWB + 25088)         // 76288 B -> 2 CTAs/SM

__global__ __launch_bounds__(256, 2)
void k_main(const float* __restrict__ A) {
    extern __shared__ __align__(16) __half sh[];
    char* shc = reinterpret_cast<char*>(sh);
    const int tid = threadIdx.x, w = tid >> 5, lane = tid & 31;
    const int wm = w >> 2, wn = w & 3;
    const int m0 = blockIdx.x*64;
    const int b  = blockIdx.y;
    const u32 sb = smem_u32(sh);

    const float* Ab = A + (size_t)b*NN*NN;
    const __half* xh = g_xThi + (size_t)b*FT*NN;
    float* stST = reinterpret_cast<float*>(shc + KM_STB);
    float* stS2 = reinterpret_cast<float*>(shc + KM_S2B);
    float* As   = reinterpret_cast<float*>(shc + KM_AB);

    float d[4][6][4];
    #pragma unroll
    for (int mt = 0; mt < 4; mt++)
        #pragma unroll
        for (int nt = 0; nt < 6; nt++)
            #pragma unroll
            for (int e = 0; e < 4; e++) d[mt][nt][e] = 0.f;

    auto stage = [&](int ch) {
        const int n0 = ch*32;
        const int p = ch & 1;
        #pragma unroll
        for (int idx = tid; idx < 2304; idx += 256) {
            if (idx < 768) {                 // X: 192 rows x 32 halves
                int row = idx >> 2, q = idx & 3;
                u32 dst = sb + (u32)((KM_X(p) + row*WSTR + q*8)*2);
                cp16(dst, xh + (size_t)row*NN + n0 + q*8);
            } else if (idx < 1792) {         // raw ST/S2T: 2 x 64 rows x 32 f32
                int j = idx - 768;
                int sel = j >> 9;
                int i = j & 511;
                int row = i >> 3, q = i & 7;
                const float* src = sel ? g_S2T : g_ST;
                u32 dst = sb + (u32)((sel ? KM_S2B : KM_STB) + (row*32 + q*4)*4);
                cp16(dst, src + (size_t)(m0+row)*NN + n0 + q*4);
            } else {                         // raw A: 32 rows x 64 f32 (stride 68)
                int j = idx - 1792;
                int row = j >> 4, q = j & 15;
                u32 dst = sb + (u32)(KM_AB + (row*68 + q*4)*4);
                cp16(dst, Ab + (size_t)(n0+row)*NN + m0 + q*4);
            }
        }
    };

    auto build = [&](int ch) {
        const int p = ch & 1;
        #pragma unroll
        for (int idx = tid; idx < 1024; idx += 256) {
            int m = idx >> 4, pp = idx & 15, n = 2*pp;
            float2 st = *reinterpret_cast<const float2*>(&stST[m*32 + n]);
            float2 s2 = *reinterpret_cast<const float2*>(&stS2[m*32 + n]);
            float a0 = As[n*68 + m], a1 = As[(n+1)*68 + m];
            __half h1x = __float2half_rn(st.x*a0*1024.f);
            __half h1y = __float2half_rn(st.y*a1*1024.f);
            __half h2x = __float2half_rn(s2.x*a0*2048.f);
            __half h2y = __float2half_rn(s2.y*a1*2048.f);
            int base = KM_W(p);
            *reinterpret_cast<__half2*>(shc + (base + m*WSTR + n)*2)      = __halves2half2(h1x, h1y);
            *reinterpret_cast<__half2*>(shc + (base + (64+m)*WSTR + n)*2) = __halves2half2(h2x, h2y);
        }
    };

    auto domma = [&](int ch) {
        const int p = ch & 1;
        const u32 wbase = sb + (u32)(KM_W(p)*2);
        const u32 xbase = sb + (u32)(KM_X(p)*2);
        #pragma unroll
        for (int ks = 0; ks < 2; ks++) {
            u32 ah[4][4], bh[6][2];
            const int arow = wm*64 + (lane & 15);
            const int acol = ks*16 + (lane >> 4)*8;
            const int brow = wn*48 + (lane & 7);
            const int bcol = ks*16 + ((lane >> 3) & 1)*8;
            #pragma unroll
            for (int nt = 0; nt < 6; nt++)
                ldsm_x2(bh[nt], xbase + (u32)(((brow + nt*8)*WSTR + bcol)*2));
            #pragma unroll
            for (int mt = 0; mt < 4; mt++)
                ldsm_x4(ah[mt], wbase + (u32)(((arow + mt*16)*WSTR + acol)*2));
            #pragma unroll
            for (int mt = 0; mt < 4; mt++)
                #pragma unroll
                for (int nt = 0; nt < 6; nt++)
                    mma_f16(d[mt][nt], ah[mt], bh[nt]);
        }
    };

    stage(0); CP_COMMIT();
    CP_WAIT(0); __syncthreads();
    build(0); __syncthreads();

    for (int c = 0; c < 64; c++) {
        if (c < 63) { stage(c+1); CP_COMMIT(); }
        domma(c);
        if (c < 63) {
            CP_WAIT(0); __syncthreads();
            build(c+1);
            __syncthreads();
        }
    }

    const float sc = 1.f / 1024.f;
    #pragma unroll
    for (int mt = 0; mt < 4; mt++)
        #pragma unroll
        for (int nt = 0; nt < 6; nt++) {
            int mrow = wm*64 + mt*16 + (lane >> 2);
            int col  = wn*48 + nt*8 + (lane & 3)*2;
            float* base = (mrow < 64) ? g_r1 : g_r2;
            size_t off = ((size_t)b*NN + m0 + (mrow & 63))*FT + col;
            *reinterpret_cast<float2*>(base + off) =
                make_float2(d[mt][nt][0]*sc, d[mt][nt][1]*sc);
            *reinterpret_cast<float2*>(base + off + 8*FT) =
                make_float2(d[mt][nt][2]*sc, d[mt][nt][3]*sc);
        }
}

// ---------------------------------------------------------------------------
// Kernel 6: theta contraction + diagonal identity term + relu
// ---------------------------------------------------------------------------
__global__ __launch_bounds__(256)
void k_theta(const float* __restrict__ x, const float* __restrict__ A,
             const float* __restrict__ theta, float* __restrict__ out) {
    extern __shared__ float smf[];
    float* r1   = smf;
    float* r2   = smf + 6144;
    float* s0   = smf + 12288;
    float* th1  = smf + 18432;
    float* th2  = smf + 18944;
    float* th02 = smf + 19456;

    const int b   = blockIdx.y;
    const int m0  = blockIdx.x * 32;
    const int tid = threadIdx.x;
    const float* xb = x + (size_t)b*NN*FT;
    const float* Ab = A + (size_t)b*NN*NN;

    for (int i = tid; i < 1536; i += 256) {
        reinterpret_cast<float4*>(r1)[i] =
            reinterpret_cast<const float4*>(g_r1 + ((size_t)b*NN + m0)*FT)[i];
        reinterpret_cast<float4*>(r2)[i] =
            reinterpret_cast<const float4*>(g_r2 + ((size_t)b*NN + m0)*FT)[i];
    }
    for (int i = tid; i < FIN*FOUT; i += 256) {
        th1[i] = theta[512 + i];
        float t2 = theta[1024 + i];
        th2[i]  = t2;
        th02[i] = theta[i] - t2;
    }
    for (int i = tid; i < 32*FT; i += 256) {
        int m = i / FT, ftc = i - m*FT;
        float dg = Ab[(size_t)(m0+m)*NN + m0 + m];
        s0[i] = dg * xb[(size_t)(m0+m)*FT + ftc];
    }
    __syncthreads();

    float* outb = out + (size_t)b*NN*FOUT*TT;
    for (int idx = tid; idx < 32*FOUT*TT; idx += 256) {
        int m = idx / (FOUT*TT);
        int r = idx - m*(FOUT*TT);
        int o = r / TT, t = r - o*TT;
        float val = 0.f;
        #pragma unroll
        for (int f = 0; f < FIN; f++) {
            int ft = f*TT + t;
            val = fmaf(r1[m*FT + ft], th1[f*FOUT + o], val);
            val = fmaf(r2[m*FT + ft], th2[f*FOUT + o], val);
            val = fmaf(s0[m*FT + ft], th02[f*FOUT + o], val);
        }
        outb[(size_t)(m0+m)*FOUT*TT + r] = fmaxf(val, 0.f);
    }
}

// ---------------------------------------------------------------------------
extern "C" void kernel_launch(void* const* d_in, const int* in_sizes, int n_in,
                              void* d_out, int out_size) {
    const float *x = nullptr, *A = nullptr, *E = nullptr, *theta = nullptr;
    for (int i = 0; i < n_in; i++) {
        switch (in_sizes[i]) {
            case BB*NN*FIN*TT:   x     = (const float*)d_in[i]; break;
            case BB*NN*NN:       A     = (const float*)d_in[i]; break;
            case NN*FIN:         E     = (const float*)d_in[i]; break;
            case 3*FIN*FOUT:     theta = (const float*)d_in[i]; break;
        }
    }
    float* out = (float*)d_out;

    const int sup_smem = (8*NN + 128 + 8*256) * (int)sizeof(float);
    cudaFuncSetAttribute(k_supports, cudaFuncAttributeMaxDynamicSharedMemorySize, sup_smem);
    k_supports<<<NN/8, 256, sup_smem>>>(E);

    k_prepS<<<dim3(32, 32), 256>>>();
    k_prepx<<<dim3(64, BB), 256>>>(x);

    const int s2_smem = 2 * S2_BUFH * 2;   // 110592 B
    cudaFuncSetAttribute(k_s2, cudaFuncAttributeMaxDynamicSharedMemorySize, s2_smem);
    k_s2<<<dim3(8, 16), 256, s2_smem>>>();

    cudaFuncSetAttribute(k_main, cudaFuncAttributeMaxDynamicSharedMemorySize, KM_SMEM);
    k_main<<<dim3(32, BB), 256, KM_SMEM>>>(A);

    const int smem_th = 19968 * (int)sizeof(float);
    cudaFuncSetAttribute(k_theta, cudaFuncAttributeMaxDynamicSharedMemorySize, smem_th);
    k_theta<<<dim3(NN/32, BB), 256, smem_th>>>(x, A, theta, out);
}